// round 14
// baseline (speedup 1.0000x reference)
#include <cuda_runtime.h>
#include <cuda_bf16.h>
#include <cstdint>
#include <cstddef>

// ============================================================================
// Attention_5480378270188 — bf16 hi/lo 3-term mma.sync (round-9 serial shape)
// k32 chunks, swizzled pad-free smem, 3-stage cp.async ring, 1 barrier/chunk,
// 256-thread CTAs, tile 128x128, warp tile 64x32, 2 CTAs/SM.
// R14: register-lean compute cores (B resident, A mt-pair blocked+overwritten)
// ============================================================================

#define DEV_INLINE __device__ __forceinline__
typedef __nv_bfloat16 bf16;

constexpr int NN = 2048;
constexpr int MM = 2048;
constexpr int DD = 1024;
constexpr float NEG = -1000000000.0f;

constexpr size_t QKV_ELEMS = (size_t)8 * 2048 * 1024;
constexpr size_t SCORE_ELEMS = (size_t)8 * 2048 * 2048;

// ---------------- device scratch --------------------------------------------
__device__ bf16 g_xqh[QKV_ELEMS], g_xql[QKV_ELEMS];
__device__ bf16 g_xkh[QKV_ELEMS], g_xkl[QKV_ELEMS];
__device__ bf16 g_xvh[QKV_ELEMS], g_xvl[QKV_ELEMS];
__device__ bf16 g_wqh[1024 * 1024], g_wql[1024 * 1024];
__device__ bf16 g_wkh[1024 * 1024], g_wkl[1024 * 1024];
__device__ bf16 g_wvh[1024 * 1024], g_wvl[1024 * 1024];
__device__ bf16 g_qhi[QKV_ELEMS], g_qlo[QKV_ELEMS];
__device__ bf16 g_khi[QKV_ELEMS], g_klo[QKV_ELEMS];
__device__ bf16 g_vhi[QKV_ELEMS], g_vlo[QKV_ELEMS];
__device__ float g_scores[SCORE_ELEMS];
__device__ bf16 g_whi[SCORE_ELEMS], g_wlo[SCORE_ELEMS];

// ---------------- stage layout (elements), k32 chunks ------------------------
constexpr int TAE   = 128 * 32;          // 4096 elems per sub-tile
constexpr int STAGE = 4 * TAE;           // 16384 elems
constexpr int SMEM3 = 3 * STAGE * 2;     // 98304 B

// ---------------- PTX helpers -----------------------------------------------
DEV_INLINE uint32_t smem_u32(const void* p) { return (uint32_t)__cvta_generic_to_shared(p); }

DEV_INLINE void cp16(void* dst, const void* src) {
    uint32_t d = smem_u32(dst);
    asm volatile("cp.async.cg.shared.global [%0], [%1], 16;\n"
                 :: "r"(d), "l"(__cvta_generic_to_global(src)) : "memory");
}
#define CP_COMMIT() asm volatile("cp.async.commit_group;\n" ::: "memory")
#define CP_WAIT1()  asm volatile("cp.async.wait_group 1;\n" ::: "memory")
#define CP_WAIT0()  asm volatile("cp.async.wait_group 0;\n" ::: "memory")

DEV_INLINE void ldsm4(uint32_t r[4], const void* p) {
    uint32_t a = smem_u32(p);
    asm volatile("ldmatrix.sync.aligned.m8n8.x4.shared.b16 {%0,%1,%2,%3}, [%4];\n"
                 : "=r"(r[0]), "=r"(r[1]), "=r"(r[2]), "=r"(r[3]) : "r"(a));
}
DEV_INLINE void ldsm4t(uint32_t r[4], const void* p) {
    uint32_t a = smem_u32(p);
    asm volatile("ldmatrix.sync.aligned.m8n8.x4.trans.shared.b16 {%0,%1,%2,%3}, [%4];\n"
                 : "=r"(r[0]), "=r"(r[1]), "=r"(r[2]), "=r"(r[3]) : "r"(a));
}
DEV_INLINE void mma16816(float c[4], const uint32_t a[4], uint32_t b0, uint32_t b1) {
    asm volatile(
        "mma.sync.aligned.m16n8k16.row.col.f32.bf16.bf16.f32 "
        "{%0,%1,%2,%3},{%4,%5,%6,%7},{%8,%9},{%0,%1,%2,%3};\n"
        : "+f"(c[0]), "+f"(c[1]), "+f"(c[2]), "+f"(c[3])
        : "r"(a[0]), "r"(a[1]), "r"(a[2]), "r"(a[3]), "r"(b0), "r"(b1));
}
DEV_INLINE void split1(float v, bf16& h, bf16& l) {
    h = __float2bfloat16(v);
    l = __float2bfloat16(v - __bfloat162float(h));
}

// swizzles (granule index permutation within a row)
DEV_INLINE int swzK(int row, int g) { return g ^ ((row >> 1) & 3); }   // 64B rows
DEV_INLINE int swzT(int row, int g) { return g ^ (row & 7); }          // 256B rows

// ---------------- compute cores: warp tile 64m x 32n, k32 --------------------
// Register-lean: B hi+lo resident (16 regs); A blocked in mt-pairs (8 regs),
// overwritten hi->lo. Same 12 ldsm / 48 mma per kk, same 3 terms.
DEV_INLINE void compute_nt32(const bf16* st, int wm, int wn, int lane,
                             float (&acc)[4][4][4]) {
    const bf16* sAh = st;
    const bf16* sAl = st + TAE;
    const bf16* sBh = st + 2 * TAE;
    const bf16* sBl = st + 3 * TAE;
#pragma unroll
    for (int kk = 0; kk < 32; kk += 16) {
        uint32_t bh[2][4], bl[2][4], a[2][4];
        const int br0 = (lane >> 4) * 8 + (lane & 7);
        const int bg = (kk >> 3) + ((lane >> 3) & 1);
#pragma unroll
        for (int p = 0; p < 2; p++) {
            int r = wn + p * 16 + br0;
            ldsm4(bh[p], sBh + r * 32 + swzK(r, bg) * 8);
            ldsm4(bl[p], sBl + r * 32 + swzK(r, bg) * 8);
        }
        const int ar = (lane & 15), ag = (kk >> 3) + (lane >> 4);
#pragma unroll
        for (int mtb = 0; mtb < 4; mtb += 2) {
#pragma unroll
            for (int j = 0; j < 2; j++) {
                int r = wm + (mtb + j) * 16 + ar;
                ldsm4(a[j], sAh + r * 32 + swzK(r, ag) * 8);
            }
#pragma unroll
            for (int j = 0; j < 2; j++)
#pragma unroll
                for (int p = 0; p < 2; p++) {
                    mma16816(acc[mtb + j][2 * p],     a[j], bh[p][0], bh[p][1]);
                    mma16816(acc[mtb + j][2 * p + 1], a[j], bh[p][2], bh[p][3]);
                    mma16816(acc[mtb + j][2 * p],     a[j], bl[p][0], bl[p][1]);
                    mma16816(acc[mtb + j][2 * p + 1], a[j], bl[p][2], bl[p][3]);
                }
#pragma unroll
            for (int j = 0; j < 2; j++) {
                int r = wm + (mtb + j) * 16 + ar;
                ldsm4(a[j], sAl + r * 32 + swzK(r, ag) * 8);
            }
#pragma unroll
            for (int j = 0; j < 2; j++)
#pragma unroll
                for (int p = 0; p < 2; p++) {
                    mma16816(acc[mtb + j][2 * p],     a[j], bh[p][0], bh[p][1]);
                    mma16816(acc[mtb + j][2 * p + 1], a[j], bh[p][2], bh[p][3]);
                }
        }
    }
}

DEV_INLINE void compute_t32(const bf16* st, int wm, int wn, int lane,
                            float (&acc)[4][4][4]) {
    const bf16* sAh = st;
    const bf16* sAl = st + TAE;
    const bf16* sBh = st + 2 * TAE;   // 32 rows x 128 elems (v, d-major)
    const bf16* sBl = st + 3 * TAE;
#pragma unroll
    for (int kk = 0; kk < 32; kk += 16) {
        uint32_t bh[2][4], bl[2][4], a[2][4];
        const int br = kk + ((lane >> 3) & 1) * 8 + (lane & 7);
        const int g0 = (wn >> 3) + (lane >> 4);
#pragma unroll
        for (int p = 0; p < 2; p++) {
            int g = g0 + p * 2;
            ldsm4t(bh[p], sBh + br * 128 + swzT(br, g) * 8);
            ldsm4t(bl[p], sBl + br * 128 + swzT(br, g) * 8);
        }
        const int ar = (lane & 15), ag = (kk >> 3) + (lane >> 4);
#pragma unroll
        for (int mtb = 0; mtb < 4; mtb += 2) {
#pragma unroll
            for (int j = 0; j < 2; j++) {
                int r = wm + (mtb + j) * 16 + ar;
                ldsm4(a[j], sAh + r * 32 + swzK(r, ag) * 8);
            }
#pragma unroll
            for (int j = 0; j < 2; j++)
#pragma unroll
                for (int p = 0; p < 2; p++) {
                    mma16816(acc[mtb + j][2 * p],     a[j], bh[p][0], bh[p][1]);
                    mma16816(acc[mtb + j][2 * p + 1], a[j], bh[p][2], bh[p][3]);
                    mma16816(acc[mtb + j][2 * p],     a[j], bl[p][0], bl[p][1]);
                    mma16816(acc[mtb + j][2 * p + 1], a[j], bl[p][2], bl[p][3]);
                }
#pragma unroll
            for (int j = 0; j < 2; j++) {
                int r = wm + (mtb + j) * 16 + ar;
                ldsm4(a[j], sAl + r * 32 + swzK(r, ag) * 8);
            }
#pragma unroll
            for (int j = 0; j < 2; j++)
#pragma unroll
                for (int p = 0; p < 2; p++) {
                    mma16816(acc[mtb + j][2 * p],     a[j], bh[p][0], bh[p][1]);
                    mma16816(acc[mtb + j][2 * p + 1], a[j], bh[p][2], bh[p][3]);
                }
        }
    }
}

// ---------------------------------------------------------------------------
// merged projection kernel: grid (8, 128, 3); z selects q/k/v
// ---------------------------------------------------------------------------
__global__ __launch_bounds__(256, 2) void proj3(const float* __restrict__ bq,
                                                const float* __restrict__ bk,
                                                const float* __restrict__ bv) {
    extern __shared__ char ds[];
    const int tid = threadIdx.x, lane = tid & 31, warp = tid >> 5;
    const int wm = (warp & 1) * 64, wn = (warp >> 1) * 32;
    const int rowBlk = blockIdx.y * 128, colBlk = blockIdx.x * 128;
    const int z = blockIdx.z;

    const bf16 *Ah, *Al, *Bh, *Bl;
    bf16 *Chi, *Clo;
    const float* bias;
    if (z == 0)      { Ah = g_xqh; Al = g_xql; Bh = g_wqh; Bl = g_wql; Chi = g_qhi; Clo = g_qlo; bias = bq; }
    else if (z == 1) { Ah = g_xkh; Al = g_xkl; Bh = g_wkh; Bl = g_wkl; Chi = g_khi; Clo = g_klo; bias = bk; }
    else             { Ah = g_xvh; Al = g_xvl; Bh = g_wvh; Bl = g_wvl; Chi = g_vhi; Clo = g_vlo; bias = bv; }

    auto issue = [&](int s, int chunk) {
        bf16* st = (bf16*)ds + s * STAGE;
        const int k0 = chunk * 32;
#pragma unroll
        for (int i = 0; i < 2; i++) {
            int u = tid + 256 * i, r = u >> 2, g = u & 3;
            int o = r * 32 + swzK(r, g) * 8;
            size_t ga = (size_t)(rowBlk + r) * 1024 + k0 + g * 8;
            size_t gb = (size_t)(colBlk + r) * 1024 + k0 + g * 8;
            cp16(st + o, Ah + ga);
            cp16(st + TAE + o, Al + ga);
            cp16(st + 2 * TAE + o, Bh + gb);
            cp16(st + 3 * TAE + o, Bl + gb);
        }
    };

    constexpr int C = 32;
    float acc[4][4][4] = {};
    issue(0, 0); CP_COMMIT();
    issue(1, 1); CP_COMMIT();
    for (int it = 0; it < C; it++) {
        if (it + 1 < C) CP_WAIT1(); else CP_WAIT0();
        __syncthreads();
        if (it + 2 < C) { issue((it + 2) % 3, it + 2); CP_COMMIT(); }
        compute_nt32((bf16*)ds + (it % 3) * STAGE, wm, wn, lane, acc);
    }

#pragma unroll
    for (int mt = 0; mt < 4; mt++)
#pragma unroll
        for (int nt = 0; nt < 4; nt++) {
            int r = rowBlk + wm + mt * 16 + (lane >> 2);
            int c = colBlk + wn + nt * 8 + (lane & 3) * 2;
            float b0 = bias[c], b1 = bias[c + 1];
            {
                bf16 h0, l0, h1, l1;
                split1(acc[mt][nt][0] + b0, h0, l0);
                split1(acc[mt][nt][1] + b1, h1, l1);
                *(__nv_bfloat162*)(Chi + (size_t)r * 1024 + c) = __halves2bfloat162(h0, h1);
                *(__nv_bfloat162*)(Clo + (size_t)r * 1024 + c) = __halves2bfloat162(l0, l1);
            }
            {
                bf16 h0, l0, h1, l1;
                split1(acc[mt][nt][2] + b0, h0, l0);
                split1(acc[mt][nt][3] + b1, h1, l1);
                *(__nv_bfloat162*)(Chi + (size_t)(r + 8) * 1024 + c) = __halves2bfloat162(h0, h1);
                *(__nv_bfloat162*)(Clo + (size_t)(r + 8) * 1024 + c) = __halves2bfloat162(l0, l1);
            }
        }
}

// ---------------------------------------------------------------------------
// score kernel: grid (16, 16, 8); z = batch  (monolithic)
// ---------------------------------------------------------------------------
__global__ __launch_bounds__(256, 2) void score512(const int* __restrict__ mask) {
    extern __shared__ char ds[];
    const int tid = threadIdx.x, lane = tid & 31, warp = tid >> 5;
    const int wm = (warp & 1) * 64, wn = (warp >> 1) * 32;
    const int rowBlk = blockIdx.y * 128, colBlk = blockIdx.x * 128;
    const int z = blockIdx.z;
    const size_t zoff = (size_t)z * 2048 * 1024;
    const bf16* Ahp = g_qhi + zoff;  const bf16* Alp = g_qlo + zoff;
    const bf16* Bhp = g_khi + zoff;  const bf16* Blp = g_klo + zoff;

    auto issue = [&](int s, int chunk) {
        bf16* st = (bf16*)ds + s * STAGE;
        const int k0 = chunk * 32;
#pragma unroll
        for (int i = 0; i < 2; i++) {
            int u = tid + 256 * i, r = u >> 2, g = u & 3;
            int o = r * 32 + swzK(r, g) * 8;
            size_t ga = (size_t)(rowBlk + r) * 1024 + k0 + g * 8;
            size_t gb = (size_t)(colBlk + r) * 1024 + k0 + g * 8;
            cp16(st + o, Ahp + ga);
            cp16(st + TAE + o, Alp + ga);
            cp16(st + 2 * TAE + o, Bhp + gb);
            cp16(st + 3 * TAE + o, Blp + gb);
        }
    };

    constexpr int C = 32;
    float acc[4][4][4] = {};
    issue(0, 0); CP_COMMIT();
    issue(1, 1); CP_COMMIT();
    for (int it = 0; it < C; it++) {
        if (it + 1 < C) CP_WAIT1(); else CP_WAIT0();
        __syncthreads();
        if (it + 2 < C) { issue((it + 2) % 3, it + 2); CP_COMMIT(); }
        compute_nt32((bf16*)ds + (it % 3) * STAGE, wm, wn, lane, acc);
    }

    float* Sg = g_scores + (size_t)z * NN * MM;
#pragma unroll
    for (int mt = 0; mt < 4; mt++)
#pragma unroll
        for (int nt = 0; nt < 4; nt++) {
            int r = rowBlk + wm + mt * 16 + (lane >> 2);
            int c = colBlk + wn + nt * 8 + (lane & 3) * 2;
            {
                int2 m = *(const int2*)(mask + (size_t)r * MM + c);
                float2 v;
                v.x = m.x ? acc[mt][nt][0] : NEG;
                v.y = m.y ? acc[mt][nt][1] : NEG;
                *(float2*)(Sg + (size_t)r * MM + c) = v;
            }
            {
                int rr = r + 8;
                int2 m = *(const int2*)(mask + (size_t)rr * MM + c);
                float2 v;
                v.x = m.x ? acc[mt][nt][2] : NEG;
                v.y = m.y ? acc[mt][nt][3] : NEG;
                *(float2*)(Sg + (size_t)rr * MM + c) = v;
            }
        }
}

// ---------------------------------------------------------------------------
// out kernel: grid (8, 16, 8). O = w·v, B via ldmatrix.trans, K=2048
// ---------------------------------------------------------------------------
__global__ __launch_bounds__(256, 2) void out512(float* __restrict__ O) {
    extern __shared__ char ds[];
    const int tid = threadIdx.x, lane = tid & 31, warp = tid >> 5;
    const int wm = (warp & 1) * 64, wn = (warp >> 1) * 32;
    const int z = blockIdx.z;
    const int rowBlk = blockIdx.y * 128, colBlk = blockIdx.x * 128;
    const bf16* wh = g_whi + (size_t)z * NN * MM;
    const bf16* wl = g_wlo + (size_t)z * NN * MM;
    const bf16* vh = g_vhi + (size_t)z * MM * DD;
    const bf16* vl = g_vlo + (size_t)z * MM * DD;

    auto issue = [&](int s, int chunk) {
        bf16* st = (bf16*)ds + s * STAGE;
        const int k0 = chunk * 32;
#pragma unroll
        for (int i = 0; i < 2; i++) {
            int u = tid + 256 * i;
            {
                int r = u >> 2, g = u & 3;
                int o = r * 32 + swzK(r, g) * 8;
                size_t ga = (size_t)(rowBlk + r) * MM + k0 + g * 8;
                cp16(st + o, wh + ga);
                cp16(st + TAE + o, wl + ga);
            }
            {
                int r = u >> 4, g = u & 15;
                int o = r * 128 + swzT(r, g) * 8;
                size_t gb = (size_t)(k0 + r) * DD + colBlk + g * 8;
                cp16(st + 2 * TAE + o, vh + gb);
                cp16(st + 3 * TAE + o, vl + gb);
            }
        }
    };

    constexpr int C = 64;
    float acc[4][4][4] = {};
    issue(0, 0); CP_COMMIT();
    issue(1, 1); CP_COMMIT();
    for (int it = 0; it < C; it++) {
        if (it + 1 < C) CP_WAIT1(); else CP_WAIT0();
        __syncthreads();
        if (it + 2 < C) { issue((it + 2) % 3, it + 2); CP_COMMIT(); }
        compute_t32((bf16*)ds + (it % 3) * STAGE, wm, wn, lane, acc);
    }

    float* Og = O + (size_t)z * NN * DD;
#pragma unroll
    for (int mt = 0; mt < 4; mt++)
#pragma unroll
        for (int nt = 0; nt < 4; nt++) {
            int r = rowBlk + wm + mt * 16 + (lane >> 2);
            int c = colBlk + wn + nt * 8 + (lane & 3) * 2;
            float2 v0; v0.x = acc[mt][nt][0]; v0.y = acc[mt][nt][1];
            *(float2*)(Og + (size_t)r * DD + c) = v0;
            float2 v1; v1.x = acc[mt][nt][2]; v1.y = acc[mt][nt][3];
            *(float2*)(Og + (size_t)(r + 8) * DD + c) = v1;
        }
}

// ---------------------------------------------------------------------------
// merged splits: inputs (rows 0..16383) and weights (rows 16384..17407)
// ---------------------------------------------------------------------------
__global__ __launch_bounds__(256, 4) void split_all(const float* __restrict__ Xq,
                                                    const float* __restrict__ Xk,
                                                    const float* __restrict__ Xv,
                                                    const float* __restrict__ Wq,
                                                    const float* __restrict__ Wk,
                                                    const float* __restrict__ Wv) {
    const float* X; bf16 *H, *L;
    size_t row;
    if (blockIdx.x < 16384) {
        row = blockIdx.x;
        if (blockIdx.y == 0)      { X = Xq; H = g_xqh; L = g_xql; }
        else if (blockIdx.y == 1) { X = Xk; H = g_xkh; L = g_xkl; }
        else                      { X = Xv; H = g_xvh; L = g_xvl; }
    } else {
        row = blockIdx.x - 16384;
        if (blockIdx.y == 0)      { X = Wq; H = g_wqh; L = g_wql; }
        else if (blockIdx.y == 1) { X = Wk; H = g_wkh; L = g_wkl; }
        else                      { X = Wv; H = g_wvh; L = g_wvl; }
    }
    int t = threadIdx.x;
    float4 v = ((const float4*)(X + row * 1024))[t];
    bf16 h0, l0, h1, l1, h2, l2, h3, l3;
    split1(v.x, h0, l0); split1(v.y, h1, l1);
    split1(v.z, h2, l2); split1(v.w, h3, l3);
    bf16* ph = H + row * 1024 + t * 4;
    bf16* pl = L + row * 1024 + t * 4;
    *(__nv_bfloat162*)(ph)     = __halves2bfloat162(h0, h1);
    *(__nv_bfloat162*)(ph + 2) = __halves2bfloat162(h2, h3);
    *(__nv_bfloat162*)(pl)     = __halves2bfloat162(l0, l1);
    *(__nv_bfloat162*)(pl + 2) = __halves2bfloat162(l2, l3);
}

// ---------------------------------------------------------------------------
// softmax: scores row -> weights hi/lo
// ---------------------------------------------------------------------------
__global__ __launch_bounds__(256, 1) void softmax_kernel() {
    const int row = blockIdx.x;
    const int tid = threadIdx.x, lane = tid & 31, warp = tid >> 5;
    const float4* S4 = (const float4*)(g_scores + (size_t)row * MM);
    float4 u0 = S4[tid * 2], u1 = S4[tid * 2 + 1];
    float x[8] = {u0.x, u0.y, u0.z, u0.w, u1.x, u1.y, u1.z, u1.w};

    float mx = x[0];
#pragma unroll
    for (int i = 1; i < 8; i++) mx = fmaxf(mx, x[i]);
#pragma unroll
    for (int o = 16; o; o >>= 1) mx = fmaxf(mx, __shfl_xor_sync(0xffffffffu, mx, o));
    __shared__ float redm[8], reds[8];
    if (lane == 0) redm[warp] = mx;
    __syncthreads();
    mx = redm[0];
#pragma unroll
    for (int i = 1; i < 8; i++) mx = fmaxf(mx, redm[i]);

    float e[8], s = 0.f;
#pragma unroll
    for (int i = 0; i < 8; i++) { e[i] = __expf(x[i] - mx); s += e[i]; }
#pragma unroll
    for (int o = 16; o; o >>= 1) s += __shfl_xor_sync(0xffffffffu, s, o);
    if (lane == 0) reds[warp] = s;
    __syncthreads();
    s = reds[0];
#pragma unroll
    for (int i = 1; i < 8; i++) s += reds[i];
    float inv = 1.0f / s;

    bf16 h[8], l[8];
#pragma unroll
    for (int i = 0; i < 8; i++) split1(e[i] * inv, h[i], l[i]);
    uint4 uh, ul;
    __nv_bfloat162* ph = reinterpret_cast<__nv_bfloat162*>(&uh);
    __nv_bfloat162* pl = reinterpret_cast<__nv_bfloat162*>(&ul);
    ph[0] = __halves2bfloat162(h[0], h[1]); ph[1] = __halves2bfloat162(h[2], h[3]);
    ph[2] = __halves2bfloat162(h[4], h[5]); ph[3] = __halves2bfloat162(h[6], h[7]);
    pl[0] = __halves2bfloat162(l[0], l[1]); pl[1] = __halves2bfloat162(l[2], l[3]);
    pl[2] = __halves2bfloat162(l[4], l[5]); pl[3] = __halves2bfloat162(l[6], l[7]);
    *(uint4*)(g_whi + (size_t)row * MM + tid * 8) = uh;
    *(uint4*)(g_wlo + (size_t)row * MM + tid * 8) = ul;
}

// ---------------------------------------------------------------------------
// Launch: strictly serial
// ---------------------------------------------------------------------------
extern "C" void kernel_launch(void* const* d_in, const int* in_sizes, int n_in,
                              void* d_out, int out_size) {
    (void)in_sizes; (void)n_in; (void)out_size;
    const float* querys = (const float*)d_in[0];
    const float* keys   = (const float*)d_in[1];
    const float* values = (const float*)d_in[2];
    const int*   mask   = (const int*)d_in[3];
    const float* Wq     = (const float*)d_in[4];
    const float* bq     = (const float*)d_in[5];
    const float* Wk     = (const float*)d_in[6];
    const float* bk     = (const float*)d_in[7];
    const float* Wv     = (const float*)d_in[8];
    const float* bv     = (const float*)d_in[9];
    float* out = (float*)d_out;

    static bool init_done = false;
    if (!init_done) {
        cudaFuncSetAttribute(proj3, cudaFuncAttributeMaxDynamicSharedMemorySize, SMEM3);
        cudaFuncSetAttribute(score512, cudaFuncAttributeMaxDynamicSharedMemorySize, SMEM3);
        cudaFuncSetAttribute(out512, cudaFuncAttributeMaxDynamicSharedMemorySize, SMEM3);
        init_done = true;
    }

    dim3 b256(256);
    split_all<<<dim3(17408, 3), b256>>>(querys, keys, values, Wq, Wk, Wv);

    proj3<<<dim3(8, 128, 3), b256, SMEM3>>>(bq, bk, bv);

    score512<<<dim3(16, 16, 8), b256, SMEM3>>>(mask);

    softmax_kernel<<<16384, b256>>>();

    out512<<<dim3(8, 16, 8), b256, SMEM3>>>(out);
}

// round 15
// speedup vs baseline: 1.0107x; 1.0107x over previous
#include <cuda_runtime.h>
#include <cuda_bf16.h>
#include <cstdint>
#include <cstddef>

// ============================================================================
// Attention_5480378270188 — bf16 hi/lo 3-term mma.sync (FINAL: round-13 config)
// k32 chunks, swizzled pad-free smem, 3-stage cp.async ring, 1 barrier/chunk,
// 256-thread CTAs, tile 128x128, warp tile 64x32, 2 CTAs/SM, serial launches.
// ============================================================================

#define DEV_INLINE __device__ __forceinline__
typedef __nv_bfloat16 bf16;

constexpr int NN = 2048;
constexpr int MM = 2048;
constexpr int DD = 1024;
constexpr float NEG = -1000000000.0f;

constexpr size_t QKV_ELEMS = (size_t)8 * 2048 * 1024;
constexpr size_t SCORE_ELEMS = (size_t)8 * 2048 * 2048;

// ---------------- device scratch --------------------------------------------
__device__ bf16 g_xqh[QKV_ELEMS], g_xql[QKV_ELEMS];
__device__ bf16 g_xkh[QKV_ELEMS], g_xkl[QKV_ELEMS];
__device__ bf16 g_xvh[QKV_ELEMS], g_xvl[QKV_ELEMS];
__device__ bf16 g_wqh[1024 * 1024], g_wql[1024 * 1024];
__device__ bf16 g_wkh[1024 * 1024], g_wkl[1024 * 1024];
__device__ bf16 g_wvh[1024 * 1024], g_wvl[1024 * 1024];
__device__ bf16 g_qhi[QKV_ELEMS], g_qlo[QKV_ELEMS];
__device__ bf16 g_khi[QKV_ELEMS], g_klo[QKV_ELEMS];
__device__ bf16 g_vhi[QKV_ELEMS], g_vlo[QKV_ELEMS];
__device__ float g_scores[SCORE_ELEMS];
__device__ bf16 g_whi[SCORE_ELEMS], g_wlo[SCORE_ELEMS];

// ---------------- stage layout (elements), k32 chunks ------------------------
constexpr int TAE   = 128 * 32;          // 4096 elems per sub-tile
constexpr int STAGE = 4 * TAE;           // 16384 elems
constexpr int SMEM3 = 3 * STAGE * 2;     // 98304 B

// ---------------- PTX helpers -----------------------------------------------
DEV_INLINE uint32_t smem_u32(const void* p) { return (uint32_t)__cvta_generic_to_shared(p); }

DEV_INLINE void cp16(void* dst, const void* src) {
    uint32_t d = smem_u32(dst);
    asm volatile("cp.async.cg.shared.global [%0], [%1], 16;\n"
                 :: "r"(d), "l"(__cvta_generic_to_global(src)) : "memory");
}
#define CP_COMMIT() asm volatile("cp.async.commit_group;\n" ::: "memory")
#define CP_WAIT1()  asm volatile("cp.async.wait_group 1;\n" ::: "memory")
#define CP_WAIT0()  asm volatile("cp.async.wait_group 0;\n" ::: "memory")

DEV_INLINE void ldsm4(uint32_t r[4], const void* p) {
    uint32_t a = smem_u32(p);
    asm volatile("ldmatrix.sync.aligned.m8n8.x4.shared.b16 {%0,%1,%2,%3}, [%4];\n"
                 : "=r"(r[0]), "=r"(r[1]), "=r"(r[2]), "=r"(r[3]) : "r"(a));
}
DEV_INLINE void ldsm4t(uint32_t r[4], const void* p) {
    uint32_t a = smem_u32(p);
    asm volatile("ldmatrix.sync.aligned.m8n8.x4.trans.shared.b16 {%0,%1,%2,%3}, [%4];\n"
                 : "=r"(r[0]), "=r"(r[1]), "=r"(r[2]), "=r"(r[3]) : "r"(a));
}
DEV_INLINE void mma16816(float c[4], const uint32_t a[4], uint32_t b0, uint32_t b1) {
    asm volatile(
        "mma.sync.aligned.m16n8k16.row.col.f32.bf16.bf16.f32 "
        "{%0,%1,%2,%3},{%4,%5,%6,%7},{%8,%9},{%0,%1,%2,%3};\n"
        : "+f"(c[0]), "+f"(c[1]), "+f"(c[2]), "+f"(c[3])
        : "r"(a[0]), "r"(a[1]), "r"(a[2]), "r"(a[3]), "r"(b0), "r"(b1));
}
DEV_INLINE void split1(float v, bf16& h, bf16& l) {
    h = __float2bfloat16(v);
    l = __float2bfloat16(v - __bfloat162float(h));
}

// swizzles (granule index permutation within a row)
DEV_INLINE int swzK(int row, int g) { return g ^ ((row >> 1) & 3); }   // 64B rows
DEV_INLINE int swzT(int row, int g) { return g ^ (row & 7); }          // 256B rows

// ---------------- compute cores: warp tile 64m x 32n, k32 (R13 schedule) -----
DEV_INLINE void compute_nt32(const bf16* st, int wm, int wn, int lane,
                             float (&acc)[4][4][4]) {
    const bf16* sAh = st;
    const bf16* sAl = st + TAE;
    const bf16* sBh = st + 2 * TAE;
    const bf16* sBl = st + 3 * TAE;
#pragma unroll
    for (int kk = 0; kk < 32; kk += 16) {
        uint32_t ah[4][4], al[4][4], b[2][4];
        const int ar = (lane & 15), ag = (kk >> 3) + (lane >> 4);
#pragma unroll
        for (int mt = 0; mt < 4; mt++) {
            int r = wm + mt * 16 + ar;
            int o = r * 32 + swzK(r, ag) * 8;
            ldsm4(ah[mt], sAh + o);
            ldsm4(al[mt], sAl + o);
        }
        const int br0 = (lane >> 4) * 8 + (lane & 7);
        const int bg = (kk >> 3) + ((lane >> 3) & 1);
#pragma unroll
        for (int p = 0; p < 2; p++) {
            int r = wn + p * 16 + br0;
            ldsm4(b[p], sBh + r * 32 + swzK(r, bg) * 8);
        }
#pragma unroll
        for (int mt = 0; mt < 4; mt++)
#pragma unroll
            for (int p = 0; p < 2; p++) {
                mma16816(acc[mt][2 * p],     ah[mt], b[p][0], b[p][1]);
                mma16816(acc[mt][2 * p + 1], ah[mt], b[p][2], b[p][3]);
            }
#pragma unroll
        for (int mt = 0; mt < 4; mt++)
#pragma unroll
            for (int p = 0; p < 2; p++) {
                mma16816(acc[mt][2 * p],     al[mt], b[p][0], b[p][1]);
                mma16816(acc[mt][2 * p + 1], al[mt], b[p][2], b[p][3]);
            }
#pragma unroll
        for (int p = 0; p < 2; p++) {
            int r = wn + p * 16 + br0;
            ldsm4(b[p], sBl + r * 32 + swzK(r, bg) * 8);
        }
#pragma unroll
        for (int mt = 0; mt < 4; mt++)
#pragma unroll
            for (int p = 0; p < 2; p++) {
                mma16816(acc[mt][2 * p],     ah[mt], b[p][0], b[p][1]);
                mma16816(acc[mt][2 * p + 1], ah[mt], b[p][2], b[p][3]);
            }
    }
}

DEV_INLINE void compute_t32(const bf16* st, int wm, int wn, int lane,
                            float (&acc)[4][4][4]) {
    const bf16* sAh = st;
    const bf16* sAl = st + TAE;
    const bf16* sBh = st + 2 * TAE;   // 32 rows x 128 elems (v, d-major)
    const bf16* sBl = st + 3 * TAE;
#pragma unroll
    for (int kk = 0; kk < 32; kk += 16) {
        uint32_t ah[4][4], al[4][4], b[2][4];
        const int ar = (lane & 15), ag = (kk >> 3) + (lane >> 4);
#pragma unroll
        for (int mt = 0; mt < 4; mt++) {
            int r = wm + mt * 16 + ar;
            int o = r * 32 + swzK(r, ag) * 8;
            ldsm4(ah[mt], sAh + o);
            ldsm4(al[mt], sAl + o);
        }
        const int br = kk + ((lane >> 3) & 1) * 8 + (lane & 7);
        const int g0 = (wn >> 3) + (lane >> 4);
#pragma unroll
        for (int p = 0; p < 2; p++) {
            int g = g0 + p * 2;
            ldsm4t(b[p], sBh + br * 128 + swzT(br, g) * 8);
        }
#pragma unroll
        for (int mt = 0; mt < 4; mt++)
#pragma unroll
            for (int p = 0; p < 2; p++) {
                mma16816(acc[mt][2 * p],     ah[mt], b[p][0], b[p][1]);
                mma16816(acc[mt][2 * p + 1], ah[mt], b[p][2], b[p][3]);
            }
#pragma unroll
        for (int mt = 0; mt < 4; mt++)
#pragma unroll
            for (int p = 0; p < 2; p++) {
                mma16816(acc[mt][2 * p],     al[mt], b[p][0], b[p][1]);
                mma16816(acc[mt][2 * p + 1], al[mt], b[p][2], b[p][3]);
            }
#pragma unroll
        for (int p = 0; p < 2; p++) {
            int g = g0 + p * 2;
            ldsm4t(b[p], sBl + br * 128 + swzT(br, g) * 8);
        }
#pragma unroll
        for (int mt = 0; mt < 4; mt++)
#pragma unroll
            for (int p = 0; p < 2; p++) {
                mma16816(acc[mt][2 * p],     ah[mt], b[p][0], b[p][1]);
                mma16816(acc[mt][2 * p + 1], ah[mt], b[p][2], b[p][3]);
            }
    }
}

// ---------------------------------------------------------------------------
// merged projection kernel: grid (8, 128, 3); z selects q/k/v
// ---------------------------------------------------------------------------
__global__ __launch_bounds__(256, 2) void proj3(const float* __restrict__ bq,
                                                const float* __restrict__ bk,
                                                const float* __restrict__ bv) {
    extern __shared__ char ds[];
    const int tid = threadIdx.x, lane = tid & 31, warp = tid >> 5;
    const int wm = (warp & 1) * 64, wn = (warp >> 1) * 32;
    const int rowBlk = blockIdx.y * 128, colBlk = blockIdx.x * 128;
    const int z = blockIdx.z;

    const bf16 *Ah, *Al, *Bh, *Bl;
    bf16 *Chi, *Clo;
    const float* bias;
    if (z == 0)      { Ah = g_xqh; Al = g_xql; Bh = g_wqh; Bl = g_wql; Chi = g_qhi; Clo = g_qlo; bias = bq; }
    else if (z == 1) { Ah = g_xkh; Al = g_xkl; Bh = g_wkh; Bl = g_wkl; Chi = g_khi; Clo = g_klo; bias = bk; }
    else             { Ah = g_xvh; Al = g_xvl; Bh = g_wvh; Bl = g_wvl; Chi = g_vhi; Clo = g_vlo; bias = bv; }

    auto issue = [&](int s, int chunk) {
        bf16* st = (bf16*)ds + s * STAGE;
        const int k0 = chunk * 32;
#pragma unroll
        for (int i = 0; i < 2; i++) {
            int u = tid + 256 * i, r = u >> 2, g = u & 3;
            int o = r * 32 + swzK(r, g) * 8;
            size_t ga = (size_t)(rowBlk + r) * 1024 + k0 + g * 8;
            size_t gb = (size_t)(colBlk + r) * 1024 + k0 + g * 8;
            cp16(st + o, Ah + ga);
            cp16(st + TAE + o, Al + ga);
            cp16(st + 2 * TAE + o, Bh + gb);
            cp16(st + 3 * TAE + o, Bl + gb);
        }
    };

    constexpr int C = 32;
    float acc[4][4][4] = {};
    issue(0, 0); CP_COMMIT();
    issue(1, 1); CP_COMMIT();
    for (int it = 0; it < C; it++) {
        if (it + 1 < C) CP_WAIT1(); else CP_WAIT0();
        __syncthreads();
        if (it + 2 < C) { issue((it + 2) % 3, it + 2); CP_COMMIT(); }
        compute_nt32((bf16*)ds + (it % 3) * STAGE, wm, wn, lane, acc);
    }

#pragma unroll
    for (int mt = 0; mt < 4; mt++)
#pragma unroll
        for (int nt = 0; nt < 4; nt++) {
            int r = rowBlk + wm + mt * 16 + (lane >> 2);
            int c = colBlk + wn + nt * 8 + (lane & 3) * 2;
            float b0 = bias[c], b1 = bias[c + 1];
            {
                bf16 h0, l0, h1, l1;
                split1(acc[mt][nt][0] + b0, h0, l0);
                split1(acc[mt][nt][1] + b1, h1, l1);
                *(__nv_bfloat162*)(Chi + (size_t)r * 1024 + c) = __halves2bfloat162(h0, h1);
                *(__nv_bfloat162*)(Clo + (size_t)r * 1024 + c) = __halves2bfloat162(l0, l1);
            }
            {
                bf16 h0, l0, h1, l1;
                split1(acc[mt][nt][2] + b0, h0, l0);
                split1(acc[mt][nt][3] + b1, h1, l1);
                *(__nv_bfloat162*)(Chi + (size_t)(r + 8) * 1024 + c) = __halves2bfloat162(h0, h1);
                *(__nv_bfloat162*)(Clo + (size_t)(r + 8) * 1024 + c) = __halves2bfloat162(l0, l1);
            }
        }
}

// ---------------------------------------------------------------------------
// score kernel: grid (16, 16, 8); z = batch  (monolithic)
// ---------------------------------------------------------------------------
__global__ __launch_bounds__(256, 2) void score512(const int* __restrict__ mask) {
    extern __shared__ char ds[];
    const int tid = threadIdx.x, lane = tid & 31, warp = tid >> 5;
    const int wm = (warp & 1) * 64, wn = (warp >> 1) * 32;
    const int rowBlk = blockIdx.y * 128, colBlk = blockIdx.x * 128;
    const int z = blockIdx.z;
    const size_t zoff = (size_t)z * 2048 * 1024;
    const bf16* Ahp = g_qhi + zoff;  const bf16* Alp = g_qlo + zoff;
    const bf16* Bhp = g_khi + zoff;  const bf16* Blp = g_klo + zoff;

    auto issue = [&](int s, int chunk) {
        bf16* st = (bf16*)ds + s * STAGE;
        const int k0 = chunk * 32;
#pragma unroll
        for (int i = 0; i < 2; i++) {
            int u = tid + 256 * i, r = u >> 2, g = u & 3;
            int o = r * 32 + swzK(r, g) * 8;
            size_t ga = (size_t)(rowBlk + r) * 1024 + k0 + g * 8;
            size_t gb = (size_t)(colBlk + r) * 1024 + k0 + g * 8;
            cp16(st + o, Ahp + ga);
            cp16(st + TAE + o, Alp + ga);
            cp16(st + 2 * TAE + o, Bhp + gb);
            cp16(st + 3 * TAE + o, Blp + gb);
        }
    };

    constexpr int C = 32;
    float acc[4][4][4] = {};
    issue(0, 0); CP_COMMIT();
    issue(1, 1); CP_COMMIT();
    for (int it = 0; it < C; it++) {
        if (it + 1 < C) CP_WAIT1(); else CP_WAIT0();
        __syncthreads();
        if (it + 2 < C) { issue((it + 2) % 3, it + 2); CP_COMMIT(); }
        compute_nt32((bf16*)ds + (it % 3) * STAGE, wm, wn, lane, acc);
    }

    float* Sg = g_scores + (size_t)z * NN * MM;
#pragma unroll
    for (int mt = 0; mt < 4; mt++)
#pragma unroll
        for (int nt = 0; nt < 4; nt++) {
            int r = rowBlk + wm + mt * 16 + (lane >> 2);
            int c = colBlk + wn + nt * 8 + (lane & 3) * 2;
            {
                int2 m = *(const int2*)(mask + (size_t)r * MM + c);
                float2 v;
                v.x = m.x ? acc[mt][nt][0] : NEG;
                v.y = m.y ? acc[mt][nt][1] : NEG;
                *(float2*)(Sg + (size_t)r * MM + c) = v;
            }
            {
                int rr = r + 8;
                int2 m = *(const int2*)(mask + (size_t)rr * MM + c);
                float2 v;
                v.x = m.x ? acc[mt][nt][2] : NEG;
                v.y = m.y ? acc[mt][nt][3] : NEG;
                *(float2*)(Sg + (size_t)rr * MM + c) = v;
            }
        }
}

// ---------------------------------------------------------------------------
// out kernel: grid (8, 16, 8). O = w·v, B via ldmatrix.trans, K=2048
// ---------------------------------------------------------------------------
__global__ __launch_bounds__(256, 2) void out512(float* __restrict__ O) {
    extern __shared__ char ds[];
    const int tid = threadIdx.x, lane = tid & 31, warp = tid >> 5;
    const int wm = (warp & 1) * 64, wn = (warp >> 1) * 32;
    const int z = blockIdx.z;
    const int rowBlk = blockIdx.y * 128, colBlk = blockIdx.x * 128;
    const bf16* wh = g_whi + (size_t)z * NN * MM;
    const bf16* wl = g_wlo + (size_t)z * NN * MM;
    const bf16* vh = g_vhi + (size_t)z * MM * DD;
    const bf16* vl = g_vlo + (size_t)z * MM * DD;

    auto issue = [&](int s, int chunk) {
        bf16* st = (bf16*)ds + s * STAGE;
        const int k0 = chunk * 32;
#pragma unroll
        for (int i = 0; i < 2; i++) {
            int u = tid + 256 * i;
            {
                int r = u >> 2, g = u & 3;
                int o = r * 32 + swzK(r, g) * 8;
                size_t ga = (size_t)(rowBlk + r) * MM + k0 + g * 8;
                cp16(st + o, wh + ga);
                cp16(st + TAE + o, wl + ga);
            }
            {
                int r = u >> 4, g = u & 15;
                int o = r * 128 + swzT(r, g) * 8;
                size_t gb = (size_t)(k0 + r) * DD + colBlk + g * 8;
                cp16(st + 2 * TAE + o, vh + gb);
                cp16(st + 3 * TAE + o, vl + gb);
            }
        }
    };

    constexpr int C = 64;
    float acc[4][4][4] = {};
    issue(0, 0); CP_COMMIT();
    issue(1, 1); CP_COMMIT();
    for (int it = 0; it < C; it++) {
        if (it + 1 < C) CP_WAIT1(); else CP_WAIT0();
        __syncthreads();
        if (it + 2 < C) { issue((it + 2) % 3, it + 2); CP_COMMIT(); }
        compute_t32((bf16*)ds + (it % 3) * STAGE, wm, wn, lane, acc);
    }

    float* Og = O + (size_t)z * NN * DD;
#pragma unroll
    for (int mt = 0; mt < 4; mt++)
#pragma unroll
        for (int nt = 0; nt < 4; nt++) {
            int r = rowBlk + wm + mt * 16 + (lane >> 2);
            int c = colBlk + wn + nt * 8 + (lane & 3) * 2;
            float2 v0; v0.x = acc[mt][nt][0]; v0.y = acc[mt][nt][1];
            *(float2*)(Og + (size_t)r * DD + c) = v0;
            float2 v1; v1.x = acc[mt][nt][2]; v1.y = acc[mt][nt][3];
            *(float2*)(Og + (size_t)(r + 8) * DD + c) = v1;
        }
}

// ---------------------------------------------------------------------------
// merged splits: inputs (rows 0..16383) and weights (rows 16384..17407)
// ---------------------------------------------------------------------------
__global__ __launch_bounds__(256, 4) void split_all(const float* __restrict__ Xq,
                                                    const float* __restrict__ Xk,
                                                    const float* __restrict__ Xv,
                                                    const float* __restrict__ Wq,
                                                    const float* __restrict__ Wk,
                                                    const float* __restrict__ Wv) {
    const float* X; bf16 *H, *L;
    size_t row;
    if (blockIdx.x < 16384) {
        row = blockIdx.x;
        if (blockIdx.y == 0)      { X = Xq; H = g_xqh; L = g_xql; }
        else if (blockIdx.y == 1) { X = Xk; H = g_xkh; L = g_xkl; }
        else                      { X = Xv; H = g_xvh; L = g_xvl; }
    } else {
        row = blockIdx.x - 16384;
        if (blockIdx.y == 0)      { X = Wq; H = g_wqh; L = g_wql; }
        else if (blockIdx.y == 1) { X = Wk; H = g_wkh; L = g_wkl; }
        else                      { X = Wv; H = g_wvh; L = g_wvl; }
    }
    int t = threadIdx.x;
    float4 v = ((const float4*)(X + row * 1024))[t];
    bf16 h0, l0, h1, l1, h2, l2, h3, l3;
    split1(v.x, h0, l0); split1(v.y, h1, l1);
    split1(v.z, h2, l2); split1(v.w, h3, l3);
    bf16* ph = H + row * 1024 + t * 4;
    bf16* pl = L + row * 1024 + t * 4;
    *(__nv_bfloat162*)(ph)     = __halves2bfloat162(h0, h1);
    *(__nv_bfloat162*)(ph + 2) = __halves2bfloat162(h2, h3);
    *(__nv_bfloat162*)(pl)     = __halves2bfloat162(l0, l1);
    *(__nv_bfloat162*)(pl + 2) = __halves2bfloat162(l2, l3);
}

// ---------------------------------------------------------------------------
// softmax: scores row -> weights hi/lo
// ---------------------------------------------------------------------------
__global__ __launch_bounds__(256, 1) void softmax_kernel() {
    const int row = blockIdx.x;
    const int tid = threadIdx.x, lane = tid & 31, warp = tid >> 5;
    const float4* S4 = (const float4*)(g_scores + (size_t)row * MM);
    float4 u0 = S4[tid * 2], u1 = S4[tid * 2 + 1];
    float x[8] = {u0.x, u0.y, u0.z, u0.w, u1.x, u1.y, u1.z, u1.w};

    float mx = x[0];
#pragma unroll
    for (int i = 1; i < 8; i++) mx = fmaxf(mx, x[i]);
#pragma unroll
    for (int o = 16; o; o >>= 1) mx = fmaxf(mx, __shfl_xor_sync(0xffffffffu, mx, o));
    __shared__ float redm[8], reds[8];
    if (lane == 0) redm[warp] = mx;
    __syncthreads();
    mx = redm[0];
#pragma unroll
    for (int i = 1; i < 8; i++) mx = fmaxf(mx, redm[i]);

    float e[8], s = 0.f;
#pragma unroll
    for (int i = 0; i < 8; i++) { e[i] = __expf(x[i] - mx); s += e[i]; }
#pragma unroll
    for (int o = 16; o; o >>= 1) s += __shfl_xor_sync(0xffffffffu, s, o);
    if (lane == 0) reds[warp] = s;
    __syncthreads();
    s = reds[0];
#pragma unroll
    for (int i = 1; i < 8; i++) s += reds[i];
    float inv = 1.0f / s;

    bf16 h[8], l[8];
#pragma unroll
    for (int i = 0; i < 8; i++) split1(e[i] * inv, h[i], l[i]);
    uint4 uh, ul;
    __nv_bfloat162* ph = reinterpret_cast<__nv_bfloat162*>(&uh);
    __nv_bfloat162* pl = reinterpret_cast<__nv_bfloat162*>(&ul);
    ph[0] = __halves2bfloat162(h[0], h[1]); ph[1] = __halves2bfloat162(h[2], h[3]);
    ph[2] = __halves2bfloat162(h[4], h[5]); ph[3] = __halves2bfloat162(h[6], h[7]);
    pl[0] = __halves2bfloat162(l[0], l[1]); pl[1] = __halves2bfloat162(l[2], l[3]);
    pl[2] = __halves2bfloat162(l[4], l[5]); pl[3] = __halves2bfloat162(l[6], l[7]);
    *(uint4*)(g_whi + (size_t)row * MM + tid * 8) = uh;
    *(uint4*)(g_wlo + (size_t)row * MM + tid * 8) = ul;
}

// ---------------------------------------------------------------------------
// Launch: strictly serial
// ---------------------------------------------------------------------------
extern "C" void kernel_launch(void* const* d_in, const int* in_sizes, int n_in,
                              void* d_out, int out_size) {
    (void)in_sizes; (void)n_in; (void)out_size;
    const float* querys = (const float*)d_in[0];
    const float* keys   = (const float*)d_in[1];
    const float* values = (const float*)d_in[2];
    const int*   mask   = (const int*)d_in[3];
    const float* Wq     = (const float*)d_in[4];
    const float* bq     = (const float*)d_in[5];
    const float* Wk     = (const float*)d_in[6];
    const float* bk     = (const float*)d_in[7];
    const float* Wv     = (const float*)d_in[8];
    const float* bv     = (const float*)d_in[9];
    float* out = (float*)d_out;

    static bool init_done = false;
    if (!init_done) {
        cudaFuncSetAttribute(proj3, cudaFuncAttributeMaxDynamicSharedMemorySize, SMEM3);
        cudaFuncSetAttribute(score512, cudaFuncAttributeMaxDynamicSharedMemorySize, SMEM3);
        cudaFuncSetAttribute(out512, cudaFuncAttributeMaxDynamicSharedMemorySize, SMEM3);
        init_done = true;
    }

    dim3 b256(256);
    split_all<<<dim3(17408, 3), b256>>>(querys, keys, values, Wq, Wk, Wv);

    proj3<<<dim3(8, 128, 3), b256, SMEM3>>>(bq, bk, bv);

    score512<<<dim3(16, 16, 8), b256, SMEM3>>>(mask);

    softmax_kernel<<<16384, b256>>>();

    out512<<<dim3(8, 16, 8), b256, SMEM3>>>(out);
}